// round 7
// baseline (speedup 1.0000x reference)
#include <cuda_runtime.h>

// Problem constants (fixed by the dataset)
#define B_ 8
#define S_ 128
#define D_ 480
#define E_ 8
#define C_ 10
#define F_ 994    // W row stride
#define NBLK 512  // grid size; all resident in wave 1 (37KB smem -> 6 blocks/SM)

// Per-row precomputed contributions.
// Cj[b,s,k]: node1 (W cols 0:480) + edge_i (W cols 960:968), keyed by j
// Ci[b,s,k]: node2 (W cols 480:960) + edge_j (W cols 968:976) + bias, keyed by i
__device__ float g_Cj[B_ * S_ * C_];
__device__ float g_Ci[B_ * S_ * C_];
__device__ int g_done;   // zero-init; reset by last block each launch
__device__ int g_fin;

typedef unsigned long long u64;

// ---- packed fp32x2 helpers (sm_103a FFMA2 path, PTX-only) -------------------
__device__ __forceinline__ u64 pack2(float lo, float hi) {
    u64 r; asm("mov.b64 %0, {%1, %2};" : "=l"(r) : "f"(lo), "f"(hi)); return r;
}
__device__ __forceinline__ void unpack2(u64 v, float& lo, float& hi) {
    asm("mov.b64 {%0, %1}, %2;" : "=f"(lo), "=f"(hi) : "l"(v));
}
__device__ __forceinline__ u64 fma2(u64 a, u64 b, u64 c) {
    u64 d; asm("fma.rn.f32x2 %0, %1, %2, %3;" : "=l"(d) : "l"(a), "l"(b), "l"(c)); return d;
}
__device__ __forceinline__ u64 add2(u64 a, u64 b) {
    u64 d; asm("add.rn.f32x2 %0, %1, %2;" : "=l"(d) : "l"(a), "l"(b)); return d;
}

// ---------------------------------------------------------------------------
// Fused kernel: 512 blocks x 128 threads (4 warps). Block bid owns the two
// (b,i) rows bi0=2*bid, bi0+1.
//   Phase A (no sync): stage label/wp rows + epilogue weights into smem.
//   Phase B: 4 warps = precompute tasks (row bi0 + w/2, part w&1) -> g_Cj/g_Ci.
//   Spin barrier across all 512 blocks.
//   Phase C: load Cj (batch) + Ci (2 rows) via __ldcg, R6 combine math,
//            dense float4 store.
// ---------------------------------------------------------------------------
__global__ __launch_bounds__(128)
void fused_kernel(const float* __restrict__ gcn,
                  const float* __restrict__ label,
                  const float* __restrict__ wp,
                  const float* __restrict__ W,
                  const float* __restrict__ bias,
                  float* __restrict__ out) {
    __shared__ __align__(16) float sLab[2][S_ * 11];   // stride 11 (odd)
    __shared__ __align__(16) float sWp[2][S_ * 9];     // stride 9 (odd)
    __shared__ __align__(16) float sCj[S_ * C_];       // linear, stride 10
    __shared__ __align__(16) float sOut[2][S_ * C_];
    __shared__ __align__(16) u64 sWw[18][5];           // {W[2h][col_f], W[2h+1][col_f]}
    __shared__ __align__(16) float sCi[2][C_];

    int t = threadIdx.x;
    int bid = blockIdx.x;
    int bi0 = bid * 2;
    int b = bi0 >> 7;

    // ================= Phase A: stage feats + weights (independent of precompute)
    if (t < 90) {
        int f = t / 5, h = t - 5 * f;
        int col = (f < 8) ? (976 + f) : (984 + (f - 8));
        sWw[f][h] = pack2(W[(2 * h) * F_ + col], W[(2 * h + 1) * F_ + col]);
    }
    // label: 2 rows = 640 float4, scatter to stride-11 layout
    {
        const float4* src = reinterpret_cast<const float4*>(label + (size_t)bi0 * S_ * C_);
#pragma unroll
        for (int q = t; q < 640; q += 128) {
            float4 v = src[q];
            int p = 4 * q;
            int r0 = p / (S_ * C_);  int m0 = p - r0 * (S_ * C_);
            int j0 = m0 / C_,  c0 = m0 - j0 * C_;          // c0 even, <=8
            int p2 = p + 2;
            int r2 = p2 / (S_ * C_); int m2 = p2 - r2 * (S_ * C_);
            int j2 = m2 / C_,  c2 = m2 - j2 * C_;
            sLab[r0][j0 * 11 + c0]     = v.x;
            sLab[r0][j0 * 11 + c0 + 1] = v.y;
            sLab[r2][j2 * 11 + c2]     = v.z;
            sLab[r2][j2 * 11 + c2 + 1] = v.w;
        }
    }
    // wp: 2 rows = 512 float4, scatter to stride-9 layout
    {
        const float4* src = reinterpret_cast<const float4*>(wp + (size_t)bi0 * S_ * E_);
#pragma unroll
        for (int q = t; q < 512; q += 128) {
            float4 v = src[q];
            int p = 4 * q;
            int r = p >> 10;  int m = p & 1023;
            int j = m >> 3,   e = m & 7;                   // e in {0,4}
            float* dst = &sWp[r][j * 9 + e];
            dst[0] = v.x; dst[1] = v.y; dst[2] = v.z; dst[3] = v.w;
        }
    }

    // ================= Phase B: precompute (4 warps = 2 rows x 2 parts)
    {
        int warp = t >> 5, lane = t & 31;
        int row = bi0 + (warp >> 1);
        int part = warp & 1;                   // 0: Cj (cols 0:480), 1: Ci (480:960)
        const float* g = gcn + (size_t)row * D_;
        const float* Wb = W + part * 480;

        u64 acc[C_];
#pragma unroll
        for (int k = 0; k < C_; k++) acc[k] = 0ull;

#pragma unroll
        for (int it = 0; it < 3; it++) {       // d = 0..383
            int d = it * 128 + lane * 4;
            float4 gv = *reinterpret_cast<const float4*>(g + d);
            u64 gl = pack2(gv.x, gv.y), gh = pack2(gv.z, gv.w);
#pragma unroll
            for (int k = 0; k < C_; k++) {
                const float* wr = Wb + k * F_ + d;
                acc[k] = fma2(gl, *reinterpret_cast<const u64*>(wr), acc[k]);
                acc[k] = fma2(gh, *reinterpret_cast<const u64*>(wr + 2), acc[k]);
            }
        }
        if (lane < 24) {                       // d = 384..479
            int d = 384 + lane * 4;
            float4 gv = *reinterpret_cast<const float4*>(g + d);
            u64 gl = pack2(gv.x, gv.y), gh = pack2(gv.z, gv.w);
#pragma unroll
            for (int k = 0; k < C_; k++) {
                const float* wr = Wb + k * F_ + d;
                acc[k] = fma2(gl, *reinterpret_cast<const u64*>(wr), acc[k]);
                acc[k] = fma2(gh, *reinterpret_cast<const u64*>(wr + 2), acc[k]);
            }
        }

        float s[C_];
#pragma unroll
        for (int k = 0; k < C_; k++) { float lo, hi; unpack2(acc[k], lo, hi); s[k] = lo + hi; }
#pragma unroll
        for (int k = 0; k < C_; k++)
#pragma unroll
            for (int off = 16; off > 0; off >>= 1)
                s[k] += __shfl_down_sync(0xffffffffu, s[k], off);

        if (lane == 0) {
            int si = row & (S_ - 1);
            const float* ed = wp + (((size_t)(b * S_ + si) * S_) + si) * E_;
            float e0[E_];
#pragma unroll
            for (int e = 0; e < E_; e++) e0[e] = ed[e];
            if (part == 0) {
#pragma unroll
                for (int k = 0; k < C_; k++) {
                    float v = s[k];
#pragma unroll
                    for (int e = 0; e < E_; e++) v += e0[e] * W[k * F_ + 960 + e];
                    g_Cj[row * C_ + k] = v;
                }
            } else {
#pragma unroll
                for (int k = 0; k < C_; k++) {
                    float v = s[k] + bias[k];
#pragma unroll
                    for (int e = 0; e < E_; e++) v += e0[e] * W[k * F_ + 968 + e];
                    g_Ci[row * C_ + k] = v;
                }
            }
            __threadfence();   // make this warp's results globally visible
        }
    }
    __syncthreads();

    // ================= Grid-wide spin barrier (all 512 blocks are resident)
    if (t == 0) {
        atomicAdd(&g_done, 1);
        volatile int* p = &g_done;
        while (*p < NBLK) __nanosleep(32);
        __threadfence();
    }
    __syncthreads();

    // ================= Phase C: load Cj/Ci (L2, fresh) then combine
    {
        const float4* src = reinterpret_cast<const float4*>(g_Cj + (size_t)b * S_ * C_);
        float4* dst = reinterpret_cast<float4*>(sCj);
        for (int q = t; q < 320; q += 128) dst[q] = __ldcg(src + q);
    }
    if (t < 20) {
        sCi[t / C_][t % C_] = __ldcg(&g_Ci[(bi0 + t / C_) * C_ + t % C_]);
    }
    __syncthreads();

    int r = t >> 6;                           // row in block
    int q = t & 63;
    int i = (bi0 + r) & (S_ - 1);
    int j0 = q, j1 = q + 64;

    float f0[18], f1[18];
#pragma unroll
    for (int e = 0; e < E_; e++) {
        f0[e] = sWp[r][j0 * 9 + e];
        f1[e] = sWp[r][j1 * 9 + e];
    }
#pragma unroll
    for (int c = 0; c < C_; c++) {
        f0[8 + c] = sLab[r][j0 * 11 + c];
        f1[8 + c] = sLab[r][j1 * 11 + c];
    }
    // masks: label ch 1..3 (f=9..11) kept when j>=i; ch 4..9 (f=12..17) when i>=j
    {
        float mu0 = (j0 >= i) ? 1.f : 0.f, ml0 = (i >= j0) ? 1.f : 0.f;
        float mu1 = (j1 >= i) ? 1.f : 0.f, ml1 = (i >= j1) ? 1.f : 0.f;
        f0[9] *= mu0; f0[10] *= mu0; f0[11] *= mu0;
        f1[9] *= mu1; f1[10] *= mu1; f1[11] *= mu1;
#pragma unroll
        for (int f = 12; f < 18; f++) { f0[f] *= ml0; f1[f] *= ml1; }
    }

    u64 A0[5], A1[5];
    {
        const u64* cj0 = reinterpret_cast<const u64*>(sCj + j0 * C_);
        const u64* cj1 = reinterpret_cast<const u64*>(sCj + j1 * C_);
        const u64* ci  = reinterpret_cast<const u64*>(sCi[r]);
#pragma unroll
        for (int h = 0; h < 5; h++) {
            u64 cv = ci[h];
            A0[h] = add2(cj0[h], cv);
            A1[h] = add2(cj1[h], cv);
        }
    }

#pragma unroll
    for (int f = 0; f < 18; f++) {
        u64 p0 = pack2(f0[f], f0[f]);
        u64 p1 = pack2(f1[f], f1[f]);
#pragma unroll
        for (int h = 0; h < 5; h++) {
            u64 w = sWw[f][h];                // one LDS.64, two uses
            A0[h] = fma2(p0, w, A0[h]);
            A1[h] = fma2(p1, w, A1[h]);
        }
    }

    {
        u64* o0 = reinterpret_cast<u64*>(sOut[r] + j0 * C_);
        u64* o1 = reinterpret_cast<u64*>(sOut[r] + j1 * C_);
#pragma unroll
        for (int h = 0; h < 5; h++) { o0[h] = A0[h]; o1[h] = A1[h]; }
    }
    __syncthreads();

    // dense store: 2 rows = 640 float4
    {
        const float4* src = reinterpret_cast<const float4*>(sOut);
        float4* dst = reinterpret_cast<float4*>(out + (size_t)bi0 * S_ * C_);
#pragma unroll
        for (int q2 = t; q2 < 640; q2 += 128) dst[q2] = src[q2];
    }

    // reset counters for the next graph replay (all blocks passed the spin,
    // since g_fin increments only post-barrier)
    if (t == 0) {
        int f = atomicAdd(&g_fin, 1);
        if (f == NBLK - 1) { g_done = 0; g_fin = 0; }
    }
}

extern "C" void kernel_launch(void* const* d_in, const int* in_sizes, int n_in,
                              void* d_out, int out_size) {
    const float* gcn   = (const float*)d_in[0];   // [8,128,480]
    const float* label = (const float*)d_in[1];   // [8,128,128,10]
    const float* wp    = (const float*)d_in[2];   // [8,128,128,8]
    // d_in[3] = tensor_masks (all ones, no effect on the reference math)
    const float* W     = (const float*)d_in[4];   // [10,994]
    const float* bias  = (const float*)d_in[5];   // [10]
    float* out = (float*)d_out;                   // [8,128,128,10]

    fused_kernel<<<NBLK, 128>>>(gcn, label, wp, W, bias, out);
}